// round 14
// baseline (speedup 1.0000x reference)
#include <cuda_runtime.h>
#include <math.h>

#define NA 48
#define NS 4
#define NSHFR 16
#define NSHFA 4
#define NSHFZ 8
#define RAD_FEAT (NS * NSHFR)                     // 64
#define ANG_SUB (NSHFA * NSHFZ)                   // 32
#define NPAIRS_SP (NS * (NS + 1) / 2)             // 10
#define ANG_FEAT (NPAIRS_SP * ANG_SUB)            // 320
#define AEV_LEN (RAD_FEAT + ANG_FEAT)             // 384
#define RCR_F 5.2f
#define RCA_F 3.5f
#define PI_F 3.14159265358979323846f
#define NTHR 128
#define NWARP 4
#define CHUNK 128
#define F1STR 10          // f1 row stride (float2-aligned)
#define FULLM 0xffffffffu

__device__ __forceinline__ int triu_idx(int a, int b) {
    int lo = min(a, b), hi = max(a, b);
    return lo * NS - (lo * (lo - 1)) / 2 + (hi - lo);
}

__device__ __forceinline__ float pow_zeta(float x, float zeta, bool z32) {
    if (z32) {
        float y = x * x;  // ^2
        y = y * y;        // ^4
        y = y * y;        // ^8
        y = y * y;        // ^16
        return y * y;     // ^32
    }
    return __powf(x, zeta);
}

// decode pair index p -> (a,b), a<b among n items
__device__ __forceinline__ void decode_pair(int p, int n, int& a, int& b) {
    float fn = (float)n;
    float tt = 2.0f * fn - 1.0f;
    a = (int)(0.5f * (tt - sqrtf(fmaxf(tt * tt - 8.0f * (float)p, 0.0f))));
    while (a > 0 && p < a * n - (a * (a + 1)) / 2) a--;
    while (p >= (a + 1) * n - ((a + 1) * (a + 2)) / 2) a++;
    b = p - (a * n - (a * (a + 1)) / 2) + a + 1;
}

__global__ __launch_bounds__(NTHR, 12)
void aev_kernel(const float* __restrict__ coords,   // (M, A, 3)
                const float* __restrict__ gEtaR,
                const float* __restrict__ gShfR,    // (16,)
                const float* __restrict__ gEtaA,
                const float* __restrict__ gZeta,
                const float* __restrict__ gShfA,    // (4,)
                const float* __restrict__ gShfZ,    // (8,)
                const int*   __restrict__ species,  // (M, A)
                float* __restrict__ out)            // (M, A, 384)
{
    const int i = blockIdx.x;
    const int m = blockIdx.y;
    const int tid = threadIdx.x;
    const int lane = tid & 31;
    const int wid = tid >> 5;
    const unsigned ltm = (1u << lane) - 1u;

    __shared__ float scrd[NA * 3];                 // flat xyz
    __shared__ int   ssp[NA];
    __shared__ float shfr[NSHFR], shfa[NSHFA];
    __shared__ float cshfz[NSHFZ], sshfz[NSHFZ];
    __shared__ float s_etaR, s_etaA, s_zeta;
    __shared__ float dR[NA], qfcR[NA];             // radial list, species-sorted
    __shared__ int   cntRspw[NWARP][NS];
    __shared__ int   rstart[NS + 1];
    __shared__ int   wcntA[NWARP];
    __shared__ float avx[NA], avy[NA], avz[NA], ad[NA], afc[NA];
    __shared__ int   asp[NA];
    __shared__ float f1s[CHUNK * F1STR];           // per-warp 32-slot segments
    __shared__ float f2s[CHUNK * 5];
    __shared__ int   pre[NWARP][NPAIRS_SP + 1];    // per-warp bucket prefixes

    // ---- phase 0: load (spread across warps) ----
    if (tid < 36)
        ((float4*)scrd)[tid] = ((const float4*)(coords + (size_t)m * NA * 3))[tid];
    if (tid >= 64 && tid < 64 + NA)
        ssp[tid - 64] = species[(size_t)m * NA + (tid - 64)];
    if (tid >= 36 && tid < 52) shfr[tid - 36] = gShfR[tid - 36];
    if (tid >= 52 && tid < 56) shfa[tid - 52] = gShfA[tid - 52];
    if (tid >= 112 && tid < 120) {
        float z = gShfZ[tid - 112];
        cshfz[tid - 112] = cosf(z);
        sshfz[tid - 112] = sinf(z);
    }
    if (tid == 120) s_etaR = gEtaR[0];
    if (tid == 121) s_etaA = gEtaA[0];
    if (tid == 122) s_zeta = gZeta[0];
    __syncthreads();

    const float cx = scrd[i * 3], cy = scrd[i * 3 + 1], cz = scrd[i * 3 + 2];
    const float etaR = s_etaR, etaA = s_etaA, zeta = s_zeta;
    const bool z32 = (zeta == 32.0f);

    // ---- phase 1: compaction (uniform over 4 warps; warps 2,3 all-invalid) ----
    {
        int j = tid;
        bool valid = (j < NA) && (j != i);
        float dx = 0.f, dy = 0.f, dz = 0.f, d = 1e9f;
        int sp = 0;
        if (valid) {
            dx = scrd[j * 3] - cx;
            dy = scrd[j * 3 + 1] - cy;
            dz = scrd[j * 3 + 2] - cz;
            d = sqrtf(dx * dx + dy * dy + dz * dz);
            sp = ssp[j];
        }
        bool inR = valid && (d <= RCR_F);
        bool inA = valid && (d <= RCA_F);

        unsigned ballA = __ballot_sync(FULLM, inA);
        unsigned myb = 0;
        #pragma unroll
        for (int k = 0; k < NS; k++) {
            unsigned bk = __ballot_sync(FULLM, inR && (sp == k));
            if (lane == k) cntRspw[wid][k] = __popc(bk);
            if (sp == k) myb = bk;
        }
        int rankR = __popc(myb & ltm);
        int rankA = __popc(ballA & ltm);
        if (lane == 0) wcntA[wid] = __popc(ballA);
        __syncthreads();

        // per-warp redundant scan of species counts
        int totL = 0, ownpreL = 0;
        if (lane < NS) {
            int acc = 0;
            #pragma unroll
            for (int w = 0; w < NWARP; w++) {
                int c = cntRspw[w][lane];
                if (w == wid) ownpreL = acc;
                acc += c;
            }
            totL = acc;
        }
        int scan = totL;
        #pragma unroll
        for (int o = 1; o < 8; o <<= 1) {
            int v = __shfl_up_sync(FULLM, scan, o);
            if (lane >= o) scan += v;
        }
        int startL = scan - totL;
        if (wid == 0 && lane <= NS) rstart[lane] = startL;  // lane==NS -> total

        int radoff = __shfl_sync(FULLM, startL + ownpreL, valid ? sp : 0);
        if (inR) {
            int off = radoff + rankR;
            dR[off] = d;
            qfcR[off] = 0.25f * (0.5f * __cosf(d * (PI_F / RCR_F)) + 0.5f);
        }
        int preA = 0;
        #pragma unroll
        for (int w = 0; w < NWARP; w++) if (w < wid) preA += wcntA[w];
        if (inA) {
            int off = preA + rankA;
            avx[off] = dx; avy[off] = dy; avz[off] = dz;
            ad[off] = d;
            afc[off] = 0.5f * __cosf(d * (PI_F / RCA_F)) + 0.5f;
            asp[off] = sp;
        }
    }
    const int nA = wcntA[0] + wcntA[1] + wcntA[2] + wcntA[3];
    __syncthreads();   // lists visible

    // ---- phase 2: angular pairs; warp-local 32-slot segments, 1 sync/chunk ----
    const int npairs = nA * (nA - 1) / 2;
    const int s0 = (tid >> 3) & 3, t0 = tid & 7;
    float acc0 = 0.f, acc1 = 0.f, acc2 = 0.f;

    for (int base = 0; base < npairs; base += CHUNK) {
        if (base > 0) __syncthreads();   // protect previous chunk's scan

        int p = base + tid;
        bool pvalid = (p < npairs);
        int a = 0, b = 0, pidx = NPAIRS_SP;
        if (pvalid) {
            decode_pair(p, nA, a, b);
            pidx = triu_idx(asp[a], asp[b]);
        }

        // warp-local histogram + rank (no cross-warp dependency)
        unsigned msk = __match_any_sync(FULLM, pidx);
        int rank = __popc(msk & ltm);
        int cnt = 0;
        #pragma unroll
        for (int k = 0; k < NPAIRS_SP; k++) {
            unsigned bk = __ballot_sync(FULLM, pidx == k);
            if (lane == k) cnt = __popc(bk);
        }
        // inclusive shuffle-scan over lanes 0..9, derive exclusive
        int incl = cnt;
        #pragma unroll
        for (int o = 1; o < 16; o <<= 1) {
            int v = __shfl_up_sync(FULLM, incl, o);
            if (lane >= o) incl += v;
        }
        int excl = incl - cnt;
        if (lane < NPAIRS_SP) pre[wid][lane] = excl;
        if (lane == NPAIRS_SP - 1) pre[wid][NPAIRS_SP] = incl;

        int slotbase = __shfl_sync(FULLM, excl, pvalid ? pidx : 0);
        if (pvalid) {
            int slot = wid * 32 + slotbase + rank;

            float d1 = ad[a], d2 = ad[b];
            float dot = avx[a] * avx[b] + avy[a] * avy[b] + avz[a] * avz[b];
            float cosv = 0.95f * __fdividef(dot, fmaxf(d1, 1e-8f) * fmaxf(d2, 1e-8f));
            float sinv = sqrtf(fmaxf(1.0f - cosv * cosv, 0.0f));
            float dm = 0.5f * (d1 + d2);
            float fcj2 = 2.0f * afc[a] * afc[b];

            float2* f1p = (float2*)(f1s + slot * F1STR);
            #pragma unroll
            for (int t = 0; t < NSHFZ; t += 2) {
                float c0 = cosv * cshfz[t] + sinv * sshfz[t];
                float c1 = cosv * cshfz[t + 1] + sinv * sshfz[t + 1];
                float v0 = pow_zeta(0.5f * (1.0f + c0), zeta, z32);
                float v1 = pow_zeta(0.5f * (1.0f + c1), zeta, z32);
                f1p[t >> 1] = make_float2(v0, v1);
            }
            #pragma unroll
            for (int s = 0; s < NSHFA; s++) {
                float dd = dm - shfa[s];
                f2s[slot * 5 + s] = fcj2 * __expf(-etaA * dd * dd);
            }
        }
        __syncthreads();

        // feature accumulation: 4 warp-segments per bucket
        // pass 0: bucket wid; pass 1: bucket 4+wid; pass 2 (warps 0,1): 8,9
        #pragma unroll
        for (int w = 0; w < NWARP; w++) {
            int qb = w * 32 + pre[w][wid], qe = w * 32 + pre[w][wid + 1];
            for (int q = qb; q < qe; q++)
                acc0 += f1s[q * F1STR + t0] * f2s[q * 5 + s0];
        }
        #pragma unroll
        for (int w = 0; w < NWARP; w++) {
            int qb = w * 32 + pre[w][4 + wid], qe = w * 32 + pre[w][5 + wid];
            for (int q = qb; q < qe; q++)
                acc1 += f1s[q * F1STR + t0] * f2s[q * 5 + s0];
        }
        if (wid < 2) {
            #pragma unroll
            for (int w = 0; w < NWARP; w++) {
                int qb = w * 32 + pre[w][8 + wid], qe = w * 32 + pre[w][9 + wid];
                for (int q = qb; q < qe; q++)
                    acc2 += f1s[q * F1STR + t0] * f2s[q * 5 + s0];
            }
        }
    }

    // ---- phase 3: radial (registers -> gmem) + angular writeout ----
    float* o = out + ((size_t)m * NA + i) * AEV_LEN;
    if (tid < RAD_FEAT) {
        int sp = tid >> 4;
        float sk = shfr[tid & 15];
        float acc = 0.0f;
        int jb = rstart[sp], je = rstart[sp + 1];
        for (int j = jb; j < je; j++) {
            float t = dR[j] - sk;
            acc += qfcR[j] * __expf(-etaR * t * t);
        }
        o[tid] = acc;
    }
    o[RAD_FEAT + tid] = acc0;
    o[RAD_FEAT + 128 + tid] = acc1;
    if (tid < 64) o[RAD_FEAT + 256 + tid] = acc2;
}

extern "C" void kernel_launch(void* const* d_in, const int* in_sizes, int n_in,
                              void* d_out, int out_size) {
    const float* coords = (const float*)d_in[0];
    const float* EtaR   = (const float*)d_in[1];
    const float* ShfR   = (const float*)d_in[2];
    const float* EtaA   = (const float*)d_in[3];
    const float* Zeta   = (const float*)d_in[4];
    const float* ShfA   = (const float*)d_in[5];
    const float* ShfZ   = (const float*)d_in[6];
    const int*   spec   = (const int*)d_in[7];
    float* out = (float*)d_out;

    int MA = in_sizes[7];
    int M = MA / NA;

    dim3 grid(NA, M);
    aev_kernel<<<grid, NTHR>>>(coords, EtaR, ShfR, EtaA, Zeta, ShfA, ShfZ, spec, out);
}

// round 15
// speedup vs baseline: 1.1572x; 1.1572x over previous
#include <cuda_runtime.h>
#include <math.h>

#define NA 48
#define NS 4
#define NSHFR 16
#define NSHFA 4
#define NSHFZ 8
#define RAD_FEAT (NS * NSHFR)                     // 64
#define ANG_SUB (NSHFA * NSHFZ)                   // 32
#define NPAIRS_SP (NS * (NS + 1) / 2)             // 10
#define ANG_FEAT (NPAIRS_SP * ANG_SUB)            // 320
#define AEV_LEN (RAD_FEAT + ANG_FEAT)             // 384
#define RCR_F 5.2f
#define RCA_F 3.5f
#define PI_F 3.14159265358979323846f
#define NTHR 128
#define NWARP 4
#define CHUNK 128
#define F1STR 10
#define FULLM 0xffffffffu

__device__ __forceinline__ int triu_idx(int a, int b) {
    int lo = min(a, b), hi = max(a, b);
    return lo * NS - (lo * (lo - 1)) / 2 + (hi - lo);
}

__device__ __forceinline__ float pow_zeta(float x, float zeta, bool z32) {
    if (z32) {
        float y = x * x;  // ^2
        y = y * y;        // ^4
        y = y * y;        // ^8
        y = y * y;        // ^16
        return y * y;     // ^32
    }
    return __powf(x, zeta);
}

// decode pair index p -> (a,b), a<b among n items
__device__ __forceinline__ void decode_pair(int p, int n, int& a, int& b) {
    float fn = (float)n;
    float tt = 2.0f * fn - 1.0f;
    a = (int)(0.5f * (tt - sqrtf(fmaxf(tt * tt - 8.0f * (float)p, 0.0f))));
    while (a > 0 && p < a * n - (a * (a + 1)) / 2) a--;
    while (p >= (a + 1) * n - ((a + 1) * (a + 2)) / 2) a++;
    b = p - (a * n - (a * (a + 1)) / 2) + a + 1;
}

__global__ __launch_bounds__(NTHR, 12)
void aev_kernel(const float* __restrict__ coords,   // (M, A, 3)
                const float* __restrict__ gEtaR,
                const float* __restrict__ gShfR,    // (16,)
                const float* __restrict__ gEtaA,
                const float* __restrict__ gZeta,
                const float* __restrict__ gShfA,    // (4,)
                const float* __restrict__ gShfZ,    // (8,)
                const int*   __restrict__ species,  // (M, A)
                float* __restrict__ out)            // (M, A, 384)
{
    const int i = blockIdx.x;
    const int m = blockIdx.y;
    const int tid = threadIdx.x;
    const int lane = tid & 31;
    const int wid = tid >> 5;
    const unsigned ltm = (1u << lane) - 1u;

    __shared__ float scrd[NA * 3];                 // flat xyz
    __shared__ int   ssp[NA];
    __shared__ float shfr[NSHFR], shfa[NSHFA];
    __shared__ float cshfz[NSHFZ], sshfz[NSHFZ];
    __shared__ float s_etaR, s_etaA, s_zeta;
    __shared__ float dR[NA], qfcR[NA];             // radial list, species-sorted
    __shared__ int   cntRspw[NWARP][NS];
    __shared__ int   rstart[NS + 1];
    __shared__ int   wcntA[NWARP];
    __shared__ float avx[NA], avy[NA], avz[NA], ad[NA], afc[NA], arinv[NA];
    __shared__ int   asp[NA];
    __shared__ float f1s[CHUNK * F1STR];
    __shared__ float f2s[CHUNK * 5];
    __shared__ int   cntPw[NWARP][NPAIRS_SP];

    // ---- phase 0: load (spread across warps) ----
    if (tid < 36)
        ((float4*)scrd)[tid] = ((const float4*)(coords + (size_t)m * NA * 3))[tid];
    if (tid >= 64 && tid < 64 + NA)
        ssp[tid - 64] = species[(size_t)m * NA + (tid - 64)];
    if (tid >= 36 && tid < 52) shfr[tid - 36] = gShfR[tid - 36];
    if (tid >= 52 && tid < 56) shfa[tid - 52] = gShfA[tid - 52];
    if (tid >= 112 && tid < 120) {
        float z = gShfZ[tid - 112];
        cshfz[tid - 112] = cosf(z);
        sshfz[tid - 112] = sinf(z);
    }
    if (tid == 120) s_etaR = gEtaR[0];
    if (tid == 121) s_etaA = gEtaA[0];
    if (tid == 122) s_zeta = gZeta[0];
    __syncthreads();

    const float cx = scrd[i * 3], cy = scrd[i * 3 + 1], cz = scrd[i * 3 + 2];
    const float etaR = s_etaR, etaA = s_etaA, zeta = s_zeta;
    const bool z32 = (zeta == 32.0f);

    // ---- phase 1: compaction (uniform over 4 warps; warps 2,3 all-invalid) ----
    {
        int j = tid;
        bool valid = (j < NA) && (j != i);
        float dx = 0.f, dy = 0.f, dz = 0.f, d = 1e9f;
        int sp = 0;
        if (valid) {
            dx = scrd[j * 3] - cx;
            dy = scrd[j * 3 + 1] - cy;
            dz = scrd[j * 3 + 2] - cz;
            d = sqrtf(dx * dx + dy * dy + dz * dz);
            sp = ssp[j];
        }
        bool inR = valid && (d <= RCR_F);
        bool inA = valid && (d <= RCA_F);

        unsigned ballA = __ballot_sync(FULLM, inA);
        unsigned myb = 0;
        #pragma unroll
        for (int k = 0; k < NS; k++) {
            unsigned bk = __ballot_sync(FULLM, inR && (sp == k));
            if (lane == k) cntRspw[wid][k] = __popc(bk);
            if (sp == k) myb = bk;
        }
        int rankR = __popc(myb & ltm);
        int rankA = __popc(ballA & ltm);
        if (lane == 0) wcntA[wid] = __popc(ballA);
        __syncthreads();

        // per-warp redundant scan of species counts
        int totL = 0, ownpreL = 0;
        if (lane < NS) {
            int acc = 0;
            #pragma unroll
            for (int w = 0; w < NWARP; w++) {
                int c = cntRspw[w][lane];
                if (w == wid) ownpreL = acc;
                acc += c;
            }
            totL = acc;
        }
        int scan = totL;
        #pragma unroll
        for (int o = 1; o < 8; o <<= 1) {
            int v = __shfl_up_sync(FULLM, scan, o);
            if (lane >= o) scan += v;
        }
        int startL = scan - totL;
        if (wid == 0 && lane <= NS) rstart[lane] = startL;  // lane==NS -> total

        int radoff = __shfl_sync(FULLM, startL + ownpreL, valid ? sp : 0);
        if (inR) {
            int off = radoff + rankR;
            dR[off] = d;
            qfcR[off] = 0.25f * (0.5f * __cosf(d * (PI_F / RCR_F)) + 0.5f);
        }
        int preA = 0;
        #pragma unroll
        for (int w = 0; w < NWARP; w++) if (w < wid) preA += wcntA[w];
        if (inA) {
            int off = preA + rankA;
            avx[off] = dx; avy[off] = dy; avz[off] = dz;
            ad[off] = d;
            afc[off] = 0.5f * __cosf(d * (PI_F / RCA_F)) + 0.5f;
            arinv[off] = __fdividef(1.0f, fmaxf(d, 1e-8f));
            asp[off] = sp;
        }
    }
    const int nA = wcntA[0] + wcntA[1] + wcntA[2] + wcntA[3];
    __syncthreads();   // lists visible

    // ---- phase 2: angular pairs, chunked; CTA-wide sorted slots ----
    const int npairs = nA * (nA - 1) / 2;
    const int s0 = (tid >> 3) & 3, t0 = tid & 7;
    float acc0 = 0.f, acc1 = 0.f, acc2 = 0.f;

    for (int base = 0; base < npairs; base += CHUNK) {
        if (base > 0) __syncthreads();   // protect previous chunk's scan

        int p = base + tid;
        bool pvalid = (p < npairs);
        int a = 0, b = 0, pidx = NPAIRS_SP;
        if (pvalid) {
            decode_pair(p, nA, a, b);
            pidx = triu_idx(asp[a], asp[b]);
        }

        unsigned msk = __match_any_sync(FULLM, pidx);
        int rank = __popc(msk & ltm);
        #pragma unroll
        for (int k = 0; k < NPAIRS_SP; k++) {
            unsigned bk = __ballot_sync(FULLM, pidx == k);
            if (lane == k) cntPw[wid][k] = __popc(bk);
        }
        __syncthreads();

        // every warp: scan of cntPw over warps + bucket starts, in registers
        int totP = 0, ownpreP = 0;
        if (lane < NPAIRS_SP) {
            int acc = 0;
            #pragma unroll
            for (int w = 0; w < NWARP; w++) {
                int c = cntPw[w][lane];
                if (w == wid) ownpreP = acc;
                acc += c;
            }
            totP = acc;
        }
        int scan = totP;
        #pragma unroll
        for (int o = 1; o < 16; o <<= 1) {
            int v = __shfl_up_sync(FULLM, scan, o);
            if (lane >= o) scan += v;
        }
        int startP = scan - totP;
        int endP = scan;

        int slotbase = __shfl_sync(FULLM, startP + ownpreP, pvalid ? pidx : 0);
        if (pvalid) {
            int slot = slotbase + rank;

            float d1 = ad[a], d2 = ad[b];
            float dot = avx[a] * avx[b] + avy[a] * avy[b] + avz[a] * avz[b];
            float cosv = 0.95f * dot * arinv[a] * arinv[b];
            float sinv = sqrtf(fmaxf(1.0f - cosv * cosv, 0.0f));
            float dm = 0.5f * (d1 + d2);
            float fcj2 = 2.0f * afc[a] * afc[b];

            float2* f1p = (float2*)(f1s + slot * F1STR);
            #pragma unroll
            for (int t = 0; t < NSHFZ; t += 2) {
                float c0 = cosv * cshfz[t] + sinv * sshfz[t];
                float c1 = cosv * cshfz[t + 1] + sinv * sshfz[t + 1];
                float v0 = pow_zeta(0.5f * (1.0f + c0), zeta, z32);
                float v1 = pow_zeta(0.5f * (1.0f + c1), zeta, z32);
                f1p[t >> 1] = make_float2(v0, v1);
            }
            #pragma unroll
            for (int s = 0; s < NSHFA; s++) {
                float dd = dm - shfa[s];
                f2s[slot * 5 + s] = fcj2 * __expf(-etaA * dd * dd);
            }
        }
        __syncthreads();

        // feature accumulation: warp w -> bucket w, then 4+w; warps 0,1 -> 8,9
        // 2x unrolled, dual accumulators
        {
            int qb = __shfl_sync(FULLM, startP, wid);
            int qe = __shfl_sync(FULLM, endP, wid);
            float xa = 0.f, xb = 0.f;
            int q = qb;
            for (; q + 1 < qe; q += 2) {
                xa += f1s[q * F1STR + t0] * f2s[q * 5 + s0];
                xb += f1s[(q + 1) * F1STR + t0] * f2s[(q + 1) * 5 + s0];
            }
            if (q < qe) xa += f1s[q * F1STR + t0] * f2s[q * 5 + s0];
            acc0 += xa + xb;
        }
        {
            int qb = __shfl_sync(FULLM, startP, 4 + wid);
            int qe = __shfl_sync(FULLM, endP, 4 + wid);
            float xa = 0.f, xb = 0.f;
            int q = qb;
            for (; q + 1 < qe; q += 2) {
                xa += f1s[q * F1STR + t0] * f2s[q * 5 + s0];
                xb += f1s[(q + 1) * F1STR + t0] * f2s[(q + 1) * 5 + s0];
            }
            if (q < qe) xa += f1s[q * F1STR + t0] * f2s[q * 5 + s0];
            acc1 += xa + xb;
        }
        if (wid < 2) {
            int qb = __shfl_sync(FULLM, startP, 8 + wid);
            int qe = __shfl_sync(FULLM, endP, 8 + wid);
            float xa = 0.f, xb = 0.f;
            int q = qb;
            for (; q + 1 < qe; q += 2) {
                xa += f1s[q * F1STR + t0] * f2s[q * 5 + s0];
                xb += f1s[(q + 1) * F1STR + t0] * f2s[(q + 1) * 5 + s0];
            }
            if (q < qe) xa += f1s[q * F1STR + t0] * f2s[q * 5 + s0];
            acc2 += xa + xb;
        }
    }

    // ---- phase 3: radial (registers -> gmem) + angular writeout ----
    float* o = out + ((size_t)m * NA + i) * AEV_LEN;
    if (tid < RAD_FEAT) {
        int sp = tid >> 4;
        float sk = shfr[tid & 15];
        float acc = 0.0f;
        int jb = rstart[sp], je = rstart[sp + 1];
        for (int j = jb; j < je; j++) {
            float t = dR[j] - sk;
            acc += qfcR[j] * __expf(-etaR * t * t);
        }
        o[tid] = acc;
    }
    o[RAD_FEAT + tid] = acc0;
    o[RAD_FEAT + 128 + tid] = acc1;
    if (tid < 64) o[RAD_FEAT + 256 + tid] = acc2;
}

extern "C" void kernel_launch(void* const* d_in, const int* in_sizes, int n_in,
                              void* d_out, int out_size) {
    const float* coords = (const float*)d_in[0];
    const float* EtaR   = (const float*)d_in[1];
    const float* ShfR   = (const float*)d_in[2];
    const float* EtaA   = (const float*)d_in[3];
    const float* Zeta   = (const float*)d_in[4];
    const float* ShfA   = (const float*)d_in[5];
    const float* ShfZ   = (const float*)d_in[6];
    const int*   spec   = (const int*)d_in[7];
    float* out = (float*)d_out;

    int MA = in_sizes[7];
    int M = MA / NA;

    dim3 grid(NA, M);
    aev_kernel<<<grid, NTHR>>>(coords, EtaR, ShfR, EtaA, Zeta, ShfA, ShfZ, spec, out);
}